// round 2
// baseline (speedup 1.0000x reference)
#include <cuda_runtime.h>
#include <math.h>

// ---- problem constants ----
#define BB 8
#define TT 256
#define EE 512
#define FF 2048
#define DD 256
#define NN 2048
#define LL 2
#define VV 32000
#define HMM 4
#define HDD 64
#define HAA 8
#define DHH 64
#define IFF 1028
#define TOPKK 8
#define MAXSEL 64

// ---- scratch (device globals; no allocations allowed) ----
__device__ float g_x[BB*TT*EE];
__device__ float g_h[BB*TT*EE];
__device__ float g_q[BB*TT*EE];
__device__ float g_k[BB*TT*EE];
__device__ float g_v[BB*TT*EE];
__device__ float g_o[BB*TT*EE];
__device__ float g_s[BB*HAA*TT*TT];
__device__ float g_u[BB*TT*FF];
__device__ float g_iface[BB*TT*IFF];
__device__ float g_mem[BB*NN*HMM*HDD];
__device__ float g_rv[BB*DD];
__device__ float g_rvall[BB*TT*DD];
__device__ float g_ifc[BB*IFF];
__device__ float g_sim[2*BB*HMM*NN];

__device__ __forceinline__ float gelu_f(float x){
    float x3 = x*x*x;
    return 0.5f*x*(1.0f+tanhf(0.7978845608028654f*(x+0.044715f*x3)));
}
__device__ __forceinline__ float sigmoid_f(float x){ return 1.0f/(1.0f+expf(-x)); }
__device__ __forceinline__ float softplus_clip(float x){
    float sp = fmaxf(x,0.0f) + log1pf(expf(-fabsf(x)));
    return fminf(fmaxf(sp,1.0f),20.0f);
}

// ---- embedding ----
__global__ void embed_kernel(const int* __restrict__ ids,
                             const float* __restrict__ emb,
                             const float* __restrict__ pos){
    int bt = blockIdx.x;
    int t = bt & (TT-1);
    int id = ids[bt];
    for (int e = threadIdx.x; e < EE; e += 256)
        g_x[(size_t)bt*EE + e] = emb[(size_t)id*EE + e] + pos[(size_t)t*EE + e];
}

// ---- layernorm (one block per row, E=512) ----
__global__ void ln_kernel(const float* __restrict__ x, const float* __restrict__ g,
                          const float* __restrict__ bb, float* __restrict__ out){
    int row = blockIdx.x, tid = threadIdx.x;
    __shared__ float red[256];
    const float* xr = x + (size_t)row*EE;
    float v0 = xr[tid], v1 = xr[tid+256];
    red[tid] = v0+v1; __syncthreads();
    for (int s=128;s>0;s>>=1){ if (tid<s) red[tid]+=red[tid+s]; __syncthreads(); }
    float m = red[0] * (1.0f/EE);
    __syncthreads();
    float d0=v0-m, d1=v1-m;
    red[tid] = d0*d0 + d1*d1; __syncthreads();
    for (int s=128;s>0;s>>=1){ if (tid<s) red[tid]+=red[tid+s]; __syncthreads(); }
    float rs = rsqrtf(red[0]*(1.0f/EE) + 1e-5f);
    out[(size_t)row*EE + tid]       = d0*rs*g[tid]     + bb[tid];
    out[(size_t)row*EE + tid + 256] = d1*rs*g[tid+256] + bb[tid+256];
}

// ---- generic SGEMM: C[M,N] (+)= A[M,K] @ B[K,N] (+bias)(gelu). K % 8 == 0. ----
template<bool ACC, bool GELU, bool BIAS>
__global__ void sgemm_kernel(const float* __restrict__ A, const float* __restrict__ Bm,
                             const float* __restrict__ bias, float* __restrict__ C,
                             int M, int N, int K)
{
    __shared__ float As[8][128];
    __shared__ float Bs[8][128];
    int tid = threadIdx.x;
    int bm = blockIdx.y*128, bn = blockIdx.x*128;
    int tx = tid & 15, ty = tid >> 4;
    float acc[8][8];
    #pragma unroll
    for (int i=0;i<8;i++){
        #pragma unroll
        for (int j=0;j<8;j++) acc[i][j]=0.f;
    }
    int arow = tid >> 1, acol = (tid & 1)*4;
    int brow = tid >> 5, bcol = (tid & 31)*4;
    const float* Ap = A + (size_t)(bm+arow)*K + acol;
    const float* Bp = Bm + (size_t)brow*N + bn + bcol;
    bool aok = (bm+arow) < M;
    int gcol = bn + bcol;
    bool bfast = (gcol + 3) < N;

    for (int k0=0; k0<K; k0+=8){
        float4 av = make_float4(0.f,0.f,0.f,0.f);
        if (aok) av = *reinterpret_cast<const float4*>(Ap);
        As[acol+0][arow]=av.x; As[acol+1][arow]=av.y;
        As[acol+2][arow]=av.z; As[acol+3][arow]=av.w;
        float4 bv;
        if (bfast) bv = *reinterpret_cast<const float4*>(Bp);
        else {
            bv.x = (gcol+0<N)?Bp[0]:0.f;
            bv.y = (gcol+1<N)?Bp[1]:0.f;
            bv.z = (gcol+2<N)?Bp[2]:0.f;
            bv.w = (gcol+3<N)?Bp[3]:0.f;
        }
        *reinterpret_cast<float4*>(&Bs[brow][bcol]) = bv;
        __syncthreads();
        #pragma unroll
        for (int kk=0;kk<8;kk++){
            float ar[8], br[8];
            *(float4*)&ar[0] = *(const float4*)&As[kk][ty*8];
            *(float4*)&ar[4] = *(const float4*)&As[kk][ty*8+4];
            *(float4*)&br[0] = *(const float4*)&Bs[kk][tx*8];
            *(float4*)&br[4] = *(const float4*)&Bs[kk][tx*8+4];
            #pragma unroll
            for (int i=0;i<8;i++){
                #pragma unroll
                for (int j=0;j<8;j++) acc[i][j] += ar[i]*br[j];
            }
        }
        __syncthreads();
        Ap += 8; Bp += (size_t)8*N;
    }
    #pragma unroll
    for (int i=0;i<8;i++){
        int r = bm + ty*8 + i;
        if (r >= M) continue;
        #pragma unroll
        for (int j=0;j<8;j++){
            int c = bn + tx*8 + j;
            if (c >= N) continue;
            float v = acc[i][j];
            if (BIAS) v += bias[c];
            if (GELU) v = gelu_f(v);
            size_t idx = (size_t)r*N + c;
            if (ACC) v += C[idx];
            C[idx] = v;
        }
    }
}

// ---- attention: scores S = QK^T/8 with causal mask ----
__global__ void attn_s_kernel(){
    int bh = blockIdx.y;
    int b = bh >> 3, h = bh & 7;
    int qt = blockIdx.x >> 3, kt = blockIdx.x & 7;
    __shared__ float Qs[32][65];
    __shared__ float Ks[32][65];
    int tid = threadIdx.x;
    {
        int r = tid >> 3, c = (tid & 7)*8;
        const float* qsrc = g_q + ((size_t)(b*TT + qt*32 + r))*EE + h*DHH + c;
        const float* ksrc = g_k + ((size_t)(b*TT + kt*32 + r))*EE + h*DHH + c;
        float4 q0 = *(const float4*)qsrc, q1 = *(const float4*)(qsrc+4);
        float4 k0 = *(const float4*)ksrc, k1 = *(const float4*)(ksrc+4);
        Qs[r][c+0]=q0.x; Qs[r][c+1]=q0.y; Qs[r][c+2]=q0.z; Qs[r][c+3]=q0.w;
        Qs[r][c+4]=q1.x; Qs[r][c+5]=q1.y; Qs[r][c+6]=q1.z; Qs[r][c+7]=q1.w;
        Ks[r][c+0]=k0.x; Ks[r][c+1]=k0.y; Ks[r][c+2]=k0.z; Ks[r][c+3]=k0.w;
        Ks[r][c+4]=k1.x; Ks[r][c+5]=k1.y; Ks[r][c+6]=k1.z; Ks[r][c+7]=k1.w;
    }
    __syncthreads();
    int r = tid & 31, gq = tid >> 5;
    float a0=0,a1=0,a2=0,a3=0;
    #pragma unroll
    for (int kk=0;kk<64;kk++){
        float qv = Qs[r][kk];
        a0 += qv*Ks[gq*4+0][kk];
        a1 += qv*Ks[gq*4+1][kk];
        a2 += qv*Ks[gq*4+2][kk];
        a3 += qv*Ks[gq*4+3][kk];
    }
    int qrow = qt*32 + r;
    int kc = kt*32 + gq*4;
    float* srow = g_s + ((size_t)bh*TT + qrow)*TT + kc;
    srow[0] = (kc+0<=qrow)? a0*0.125f : -1e30f;
    srow[1] = (kc+1<=qrow)? a1*0.125f : -1e30f;
    srow[2] = (kc+2<=qrow)? a2*0.125f : -1e30f;
    srow[3] = (kc+3<=qrow)? a3*0.125f : -1e30f;
}

// ---- attention: row softmax in-place on g_s ----
__global__ void softmax_kernel(){
    int row = blockIdx.x, tid = threadIdx.x;
    __shared__ float red[256];
    float* sp = g_s + (size_t)row*TT;
    float v = sp[tid];
    red[tid]=v; __syncthreads();
    for (int s=128;s>0;s>>=1){ if (tid<s) red[tid]=fmaxf(red[tid],red[tid+s]); __syncthreads(); }
    float m = red[0]; __syncthreads();
    float e = expf(v-m);
    red[tid]=e; __syncthreads();
    for (int s=128;s>0;s>>=1){ if (tid<s) red[tid]+=red[tid+s]; __syncthreads(); }
    sp[tid] = e / red[0];
}

// ---- attention: O = A @ V ----
__global__ void attn_o_kernel(){
    int bh = blockIdx.y;
    int b = bh >> 3, h = bh & 7;
    int qt = blockIdx.x;
    __shared__ float As[32][65];
    __shared__ float Vs[64][64];
    int tid = threadIdx.x;
    int d = tid & 63, qg = tid >> 6;
    float acc[8];
    #pragma unroll
    for (int i=0;i<8;i++) acc[i]=0.f;
    for (int k0=0;k0<TT;k0+=64){
        {
            int r = tid >> 3, c = (tid & 7)*8;
            const float* src = g_s + ((size_t)bh*TT + qt*32 + r)*TT + k0 + c;
            float4 a0=*(const float4*)src, a1=*(const float4*)(src+4);
            As[r][c+0]=a0.x; As[r][c+1]=a0.y; As[r][c+2]=a0.z; As[r][c+3]=a0.w;
            As[r][c+4]=a1.x; As[r][c+5]=a1.y; As[r][c+6]=a1.z; As[r][c+7]=a1.w;
        }
        #pragma unroll
        for (int i=0;i<4;i++){
            int fl = (tid + 256*i)*4;
            int r = fl >> 6, c = fl & 63;
            float4 vv = *(const float4*)(g_v + ((size_t)(b*TT + k0 + r))*EE + h*DHH + c);
            *(float4*)&Vs[r][c] = vv;
        }
        __syncthreads();
        #pragma unroll
        for (int kk=0;kk<64;kk++){
            float vv = Vs[kk][d];
            #pragma unroll
            for (int i=0;i<8;i++) acc[i] += As[qg*8+i][kk]*vv;
        }
        __syncthreads();
    }
    #pragma unroll
    for (int i=0;i<8;i++){
        int qr = qt*32 + qg*8 + i;
        g_o[((size_t)(b*TT + qr))*EE + h*DHH + d] = acc[i];
    }
}

// ---- memory init / rv init ----
__global__ void meminit_kernel(const float* __restrict__ mi){
    int idx = blockIdx.x*256 + threadIdx.x;
    g_mem[idx] = mi[idx & (NN*DD - 1)];
}
__global__ void rvzero_kernel(){
    g_rv[blockIdx.x*256 + threadIdx.x] = 0.f;
}

// ---- scan step 1: i = iface[:,t,:] + rv @ W_if_r + b_if; also record rv_all[b,t,:] ----
__global__ void scan_iface_kernel(const float* __restrict__ Wr, const float* __restrict__ bif, int t){
    int b = blockIdx.y;
    int tid = threadIdx.x;
    __shared__ float rvs[DD];
    for (int i=tid;i<DD;i+=128) rvs[i]=g_rv[b*DD+i];
    __syncthreads();
    int c = blockIdx.x*128 + tid;
    if (c < IFF){
        float acc = g_iface[((size_t)(b*TT + t))*IFF + c] + bif[c];
        #pragma unroll 4
        for (int d=0; d<DD; ++d) acc += rvs[d] * Wr[(size_t)d*IFF + c];
        g_ifc[b*IFF + c] = acc;
    }
    if (blockIdx.x < 2){
        int i = blockIdx.x*128 + tid;
        g_rvall[((size_t)(b*TT + t))*DD + i] = rvs[i];
    }
}

// ---- scan step 2: cosine similarities (read+write keys in one mem pass) ----
__global__ void scan_sim_kernel(){
    int bh = blockIdx.y;
    int b = bh >> 2, h = bh & 3;
    int tid = threadIdx.x;
    int lane = tid & 31, w = tid >> 5;
    __shared__ float knr[HDD], knw[HDD];
    if (w < 2){
        const float* key = g_ifc + b*IFF + (w? DD:0) + h*HDD;
        float v0 = key[lane], v1 = key[lane+32];
        float ss = v0*v0 + v1*v1;
        #pragma unroll
        for (int o=16;o>0;o>>=1) ss += __shfl_xor_sync(0xffffffffu, ss, o);
        float rn = rsqrtf(ss + 1e-8f);
        float* dst = w ? knw : knr;
        dst[lane] = v0*rn; dst[lane+32] = v1*rn;
    }
    __syncthreads();
    float k0r = knr[lane*2], k1r = knr[lane*2+1];
    float k0w = knw[lane*2], k1w = knw[lane*2+1];
    int nbase = blockIdx.x*256 + w*32;
    #pragma unroll 4
    for (int it=0; it<32; ++it){
        int n = nbase + it;
        const float2 m2 = *reinterpret_cast<const float2*>(
            g_mem + (((size_t)b*NN + n)*HMM + h)*HDD + lane*2);
        float ss = m2.x*m2.x + m2.y*m2.y;
        float dr = m2.x*k0r + m2.y*k1r;
        float dw = m2.x*k0w + m2.y*k1w;
        #pragma unroll
        for (int o=16;o>0;o>>=1){
            ss += __shfl_xor_sync(0xffffffffu, ss, o);
            dr += __shfl_xor_sync(0xffffffffu, dr, o);
            dw += __shfl_xor_sync(0xffffffffu, dw, o);
        }
        if (lane==0){
            float rn = rsqrtf(ss + 1e-8f);
            g_sim[(size_t)bh*NN + n] = dr*rn;
            g_sim[(size_t)BB*HMM*NN + (size_t)bh*NN + n] = dw*rn;
        }
    }
}

// ---- scan step 3: top-8 + softmax + read value + sparse memory update ----
__global__ void scan_update_kernel(const float* __restrict__ pbr, const float* __restrict__ pbw){
    int bh = blockIdx.x;
    int b = bh >> 2, h = bh & 3;
    int tid = threadIdx.x;
    __shared__ float ssim[NN];
    __shared__ float swork[NN];
    __shared__ float rval[256];
    __shared__ int   ridx[256];
    __shared__ float kvals[TOPKK];
    __shared__ int   s_cnt;
    __shared__ int   sel_idx[MAXSEL];
    __shared__ float sel_w[MAXSEL];
    __shared__ float s_inv;

    for (int phase=0; phase<2; ++phase){
        float beta = phase ? softplus_clip(*pbw) : softplus_clip(*pbr);
        const float* src = g_sim + (phase? (size_t)BB*HMM*NN : (size_t)0) + (size_t)bh*NN;
        for (int i=tid;i<NN;i+=256){ float v=src[i]; ssim[i]=v; swork[i]=v; }
        if (tid==0) s_cnt = 0;
        __syncthreads();
        // top-8 values by iterative block argmax
        for (int it=0; it<TOPKK; ++it){
            float bv = -3.4e38f; int bi = 0;
            for (int i=tid;i<NN;i+=256){ float v=swork[i]; if (v>bv){bv=v;bi=i;} }
            rval[tid]=bv; ridx[tid]=bi;
            __syncthreads();
            for (int s=128;s>0;s>>=1){
                if (tid<s && rval[tid+s]>rval[tid]){ rval[tid]=rval[tid+s]; ridx[tid]=ridx[tid+s]; }
                __syncthreads();
            }
            if (tid==0){ kvals[it]=rval[0]; swork[ridx[0]] = -3.4e38f; }
            __syncthreads();
        }
        float kth = kvals[TOPKK-1], smax = kvals[0];
        // select entries >= kth; softmax numerators
        for (int i=tid;i<NN;i+=256){
            float v = ssim[i];
            if (v >= kth){
                int p = atomicAdd(&s_cnt, 1);
                if (p < MAXSEL){ sel_idx[p]=i; sel_w[p]=expf(beta*(v-smax)); }
            }
        }
        __syncthreads();
        int cnt = min(s_cnt, MAXSEL);
        if (tid==0){
            float dsum=0.f;
            for (int j=0;j<cnt;j++) dsum += sel_w[j];
            s_inv = 1.0f/dsum;
        }
        __syncthreads();
        float invd = s_inv;
        if (phase==0){
            if (tid < HDD){
                float acc=0.f;
                for (int j=0;j<cnt;j++)
                    acc += sel_w[j]*invd * g_mem[(((size_t)b*NN + sel_idx[j])*HMM + h)*HDD + tid];
                g_rv[b*DD + h*HDD + tid] = acc;
            }
        } else {
            float gg = sigmoid_f(g_ifc[b*IFF + 4*DD + h]);
            int d = tid & 63;
            float ee = sigmoid_f(g_ifc[b*IFF + 3*DD + h*HDD + d]);
            float gv = gg * g_ifc[b*IFF + 2*DD + h*HDD + d];
            for (int j = tid>>6; j<cnt; j+=4){
                float w = sel_w[j]*invd;
                size_t mi = (((size_t)b*NN + sel_idx[j])*HMM + h)*HDD + d;
                g_mem[mi] = g_mem[mi]*(1.0f - w*ee) + w*gv;
            }
        }
        __syncthreads();
    }
}

extern "C" void kernel_launch(void* const* d_in, const int* in_sizes, int n_in,
                              void* d_out, int out_size)
{
    const int*   ids      = (const int*)  d_in[0];
    const float* emb      = (const float*)d_in[1];
    const float* pos      = (const float*)d_in[2];
    const float* ln1_g    = (const float*)d_in[3];
    const float* ln1_b    = (const float*)d_in[4];
    const float* ln2_g    = (const float*)d_in[5];
    const float* ln2_b    = (const float*)d_in[6];
    const float* Wq       = (const float*)d_in[7];
    const float* Wk       = (const float*)d_in[8];
    const float* Wv       = (const float*)d_in[9];
    const float* Wo       = (const float*)d_in[10];
    const float* W1       = (const float*)d_in[11];
    const float* b1       = (const float*)d_in[12];
    const float* W2       = (const float*)d_in[13];
    const float* b2       = (const float*)d_in[14];
    const float* lnf_g    = (const float*)d_in[15];
    const float* lnf_b    = (const float*)d_in[16];
    const float* W_if_h   = (const float*)d_in[17];
    const float* W_if_r   = (const float*)d_in[18];
    const float* b_if     = (const float*)d_in[19];
    const float* W_lg_h   = (const float*)d_in[20];
    const float* W_lg_r   = (const float*)d_in[21];
    const float* b_lg     = (const float*)d_in[22];
    const float* beta_read  = (const float*)d_in[23];
    const float* beta_write = (const float*)d_in[24];
    const float* mem_init = (const float*)d_in[25];
    float* out = (float*)d_out;

    float *px,*phh,*pq,*pk,*pv,*po,*pu,*pif,*prva;
    cudaGetSymbolAddress((void**)&px,  g_x);
    cudaGetSymbolAddress((void**)&phh, g_h);
    cudaGetSymbolAddress((void**)&pq,  g_q);
    cudaGetSymbolAddress((void**)&pk,  g_k);
    cudaGetSymbolAddress((void**)&pv,  g_v);
    cudaGetSymbolAddress((void**)&po,  g_o);
    cudaGetSymbolAddress((void**)&pu,  g_u);
    cudaGetSymbolAddress((void**)&pif, g_iface);
    cudaGetSymbolAddress((void**)&prva,g_rvall);

    const int M = BB*TT;  // 2048

    embed_kernel<<<M,256>>>(ids, emb, pos);

    for (int l=0; l<LL; ++l){
        ln_kernel<<<M,256>>>(px, ln1_g + l*EE, ln1_b + l*EE, phh);
        sgemm_kernel<false,false,false><<<dim3(4,16),256>>>(phh, Wq + (size_t)l*EE*EE, nullptr, pq, M, EE, EE);
        sgemm_kernel<false,false,false><<<dim3(4,16),256>>>(phh, Wk + (size_t)l*EE*EE, nullptr, pk, M, EE, EE);
        sgemm_kernel<false,false,false><<<dim3(4,16),256>>>(phh, Wv + (size_t)l*EE*EE, nullptr, pv, M, EE, EE);
        attn_s_kernel<<<dim3(64, BB*HAA),256>>>();
        softmax_kernel<<<BB*HAA*TT,256>>>();
        attn_o_kernel<<<dim3(8, BB*HAA),256>>>();
        sgemm_kernel<true,false,false><<<dim3(4,16),256>>>(po, Wo + (size_t)l*EE*EE, nullptr, px, M, EE, EE);
        ln_kernel<<<M,256>>>(px, ln2_g + l*EE, ln2_b + l*EE, phh);
        sgemm_kernel<false,true,true><<<dim3(16,16),256>>>(phh, W1 + (size_t)l*EE*FF, b1 + l*FF, pu, M, FF, EE);
        sgemm_kernel<true,false,true><<<dim3(4,16),256>>>(pu, W2 + (size_t)l*FF*EE, b2 + l*EE, px, M, EE, FF);
    }

    ln_kernel<<<M,256>>>(px, lnf_g, lnf_b, phh);
    sgemm_kernel<false,false,false><<<dim3(9,16),256>>>(phh, W_if_h, nullptr, pif, M, IFF, EE);
    sgemm_kernel<false,false,true><<<dim3(250,16),256>>>(phh, W_lg_h, b_lg, out, M, VV, EE);

    meminit_kernel<<<16384,256>>>(mem_init);
    rvzero_kernel<<<8,256>>>();

    for (int t=0; t<TT; ++t){
        scan_iface_kernel<<<dim3(9,BB),128>>>(W_if_r, b_if, t);
        scan_sim_kernel<<<dim3(8, BB*HMM),256>>>();
        scan_update_kernel<<<BB*HMM,256>>>(beta_read, beta_write);
    }

    // out += rv_all @ W_lg_r   (rv_all rows are [b*T + t], matching out rows)
    sgemm_kernel<true,false,false><<<dim3(250,16),256>>>(prva, W_lg_r, nullptr, out, M, VV, DD);
}

// round 3
// speedup vs baseline: 1.1219x; 1.1219x over previous
#include <cuda_runtime.h>
#include <math.h>

// ---- problem constants ----
#define BB 8
#define TT 256
#define EE 512
#define FF 2048
#define DD 256
#define NN 2048
#define LL 2
#define VV 32000
#define HMM 4
#define HDD 64
#define HAA 8
#define DHH 64
#define IFF 1028
#define TOPKK 8
#define MAXSEL 64
#define KCAT 768

// ---- scratch (device globals; no allocations allowed) ----
__device__ float g_x[BB*TT*EE];
__device__ float g_h[BB*TT*EE];
__device__ float g_q[BB*TT*EE];
__device__ float g_k[BB*TT*EE];
__device__ float g_v[BB*TT*EE];
__device__ float g_o[BB*TT*EE];
__device__ float g_s[BB*HAA*TT*TT];
__device__ float g_u[BB*TT*FF];
__device__ float g_iface[BB*TT*IFF];
__device__ float g_mem[BB*NN*HMM*HDD];
__device__ float g_rv[BB*DD];
__device__ float g_cat[BB*TT*KCAT];   // [h(512) | rv_carry(256)] per row

__device__ __forceinline__ float gelu_f(float x){
    float x3 = x*x*x;
    return 0.5f*x*(1.0f+tanhf(0.7978845608028654f*(x+0.044715f*x3)));
}
__device__ __forceinline__ float sigmoid_f(float x){ return 1.0f/(1.0f+expf(-x)); }
__device__ __forceinline__ float softplus_clip(float x){
    float sp = fmaxf(x,0.0f) + log1pf(expf(-fabsf(x)));
    return fminf(fmaxf(sp,1.0f),20.0f);
}

// ---- tf32 helpers ----
__device__ __forceinline__ void f32_split(float x, unsigned &hi, unsigned &lo){
    asm("cvt.rna.tf32.f32 %0, %1;" : "=r"(hi) : "f"(x));
    float r = x - __uint_as_float(hi);
    asm("cvt.rna.tf32.f32 %0, %1;" : "=r"(lo) : "f"(r));
}
__device__ __forceinline__ void mma_tf32(float* c, const unsigned* a, const unsigned* b){
    asm volatile("mma.sync.aligned.m16n8k8.row.col.f32.tf32.tf32.f32 "
        "{%0,%1,%2,%3}, {%4,%5,%6,%7}, {%8,%9}, {%0,%1,%2,%3};\n"
        : "+f"(c[0]), "+f"(c[1]), "+f"(c[2]), "+f"(c[3])
        : "r"(a[0]), "r"(a[1]), "r"(a[2]), "r"(a[3]), "r"(b[0]), "r"(b[1]));
}

// ---- embedding ----
__global__ void embed_kernel(const int* __restrict__ ids,
                             const float* __restrict__ emb,
                             const float* __restrict__ pos){
    int bt = blockIdx.x;
    int t = bt & (TT-1);
    int id = ids[bt];
    for (int e = threadIdx.x; e < EE; e += 256)
        g_x[(size_t)bt*EE + e] = emb[(size_t)id*EE + e] + pos[(size_t)t*EE + e];
}

// ---- layernorm (one block per row, E=512), output row stride parameterized ----
__global__ void ln_kernel(const float* __restrict__ x, const float* __restrict__ g,
                          const float* __restrict__ bb, float* __restrict__ out, int ostride){
    int row = blockIdx.x, tid = threadIdx.x;
    __shared__ float red[256];
    const float* xr = x + (size_t)row*EE;
    float v0 = xr[tid], v1 = xr[tid+256];
    red[tid] = v0+v1; __syncthreads();
    for (int s=128;s>0;s>>=1){ if (tid<s) red[tid]+=red[tid+s]; __syncthreads(); }
    float m = red[0] * (1.0f/EE);
    __syncthreads();
    float d0=v0-m, d1=v1-m;
    red[tid] = d0*d0 + d1*d1; __syncthreads();
    for (int s=128;s>0;s>>=1){ if (tid<s) red[tid]+=red[tid+s]; __syncthreads(); }
    float rs = rsqrtf(red[0]*(1.0f/EE) + 1e-5f);
    out[(size_t)row*ostride + tid]       = d0*rs*g[tid]     + bb[tid];
    out[(size_t)row*ostride + tid + 256] = d1*rs*g[tid+256] + bb[tid+256];
}

// ---- 3xTF32 tensor-core GEMM ----
// C[M,N] (+)= A[M,K](lda) @ B[K,N] (+bias)(gelu)
// B rows < Ksplit come from B1, rows >= Ksplit from B2 (for concatenated-K GEMM).
// Block tile 128x128, BK=8, 8 warps (each 64x32), double-buffered smem.
template<bool ACC, bool GELU, bool BIAS, bool NGUARD>
__global__ __launch_bounds__(256,1)
void tgemm_kernel(const float* __restrict__ A, const float* __restrict__ B1,
                  const float* __restrict__ B2, int Ksplit,
                  const float* __restrict__ bias, float* __restrict__ C,
                  int N, int K, int lda)
{
    __shared__ float As[2][8][136];
    __shared__ float Bs[2][8][136];
    int tid = threadIdx.x;
    int bm = blockIdx.y*128, bn = blockIdx.x*128;
    int warp = tid>>5, lane = tid&31;
    int wm = (warp>>2)*64, wn = (warp&3)*32;
    int gid = lane>>2, tig = lane&3;

    float c[4][4][4];
    #pragma unroll
    for (int mt=0;mt<4;mt++)
        #pragma unroll
        for (int nt=0;nt<4;nt++)
            #pragma unroll
            for (int i=0;i<4;i++) c[mt][nt][i]=0.f;

    // load assignments
    int am = tid & 127;        // A row within tile
    int ak = (tid>>7)*4;       // A k offset (0 or 4)
    int bn4 = (lane)*4;        // B col within tile (warp-level: lane*4)
    int bk  = warp;            // B k row 0..7
    const float* Ap = A + (size_t)(bm+am)*lda + ak;

    int nit = K/8;

    // helper lambda-ish: B load for k-iter "it"
    auto loadB = [&](int it)->float4 {
        int krow = it*8 + bk;
        const float* bp = (krow < Ksplit) ? (B1 + (size_t)krow*N)
                                          : (B2 + (size_t)(krow-Ksplit)*N);
        int col = bn + bn4;
        float4 bv;
        if (!NGUARD || (col+3) < N){
            bv = *reinterpret_cast<const float4*>(bp + col);
        } else {
            bv.x = (col+0<N)? bp[col+0] : 0.f;
            bv.y = (col+1<N)? bp[col+1] : 0.f;
            bv.z = (col+2<N)? bp[col+2] : 0.f;
            bv.w = (col+3<N)? bp[col+3] : 0.f;
        }
        return bv;
    };

    // first tile -> buffer 0
    {
        float4 av = *reinterpret_cast<const float4*>(Ap);
        float4 bv = loadB(0);
        As[0][ak+0][am]=av.x; As[0][ak+1][am]=av.y;
        As[0][ak+2][am]=av.z; As[0][ak+3][am]=av.w;
        *reinterpret_cast<float4*>(&Bs[0][bk][bn4]) = bv;
    }
    __syncthreads();

    for (int it=0; it<nit; ++it){
        int cur = it & 1;
        float4 av2, bv2;
        bool more = (it+1) < nit;
        if (more){
            av2 = *reinterpret_cast<const float4*>(Ap + (size_t)(it+1)*8);
            bv2 = loadB(it+1);
        }
        // fragments
        unsigned ahi[4][4], alo[4][4];
        #pragma unroll
        for (int mt=0;mt<4;mt++){
            int m0 = wm + mt*16 + gid;
            f32_split(As[cur][tig  ][m0  ], ahi[mt][0], alo[mt][0]);
            f32_split(As[cur][tig  ][m0+8], ahi[mt][1], alo[mt][1]);
            f32_split(As[cur][tig+4][m0  ], ahi[mt][2], alo[mt][2]);
            f32_split(As[cur][tig+4][m0+8], ahi[mt][3], alo[mt][3]);
        }
        unsigned bhi[4][2], blo[4][2];
        #pragma unroll
        for (int nt=0;nt<4;nt++){
            int n0 = wn + nt*8 + gid;
            f32_split(Bs[cur][tig  ][n0], bhi[nt][0], blo[nt][0]);
            f32_split(Bs[cur][tig+4][n0], bhi[nt][1], blo[nt][1]);
        }
        #pragma unroll
        for (int mt=0;mt<4;mt++){
            #pragma unroll
            for (int nt=0;nt<4;nt++){
                mma_tf32(c[mt][nt], ahi[mt], bhi[nt]);
                mma_tf32(c[mt][nt], ahi[mt], blo[nt]);
                mma_tf32(c[mt][nt], alo[mt], bhi[nt]);
            }
        }
        if (more){
            int nxt = cur ^ 1;
            As[nxt][ak+0][am]=av2.x; As[nxt][ak+1][am]=av2.y;
            As[nxt][ak+2][am]=av2.z; As[nxt][ak+3][am]=av2.w;
            *reinterpret_cast<float4*>(&Bs[nxt][bk][bn4]) = bv2;
            __syncthreads();
        }
    }

    // epilogue
    #pragma unroll
    for (int mt=0;mt<4;mt++){
        int ra = bm + wm + mt*16 + gid;
        int rb = ra + 8;
        #pragma unroll
        for (int nt=0;nt<4;nt++){
            int col = bn + wn + nt*8 + tig*2;
            #pragma unroll
            for (int q=0;q<4;q++){
                int r = (q<2)? ra : rb;
                int cc = col + (q&1);
                if (NGUARD && cc >= N) continue;
                float v = c[mt][nt][q];
                if (BIAS) v += bias[cc];
                if (GELU) v = gelu_f(v);
                size_t idx = (size_t)r*N + cc;
                if (ACC) v += C[idx];
                C[idx] = v;
            }
        }
    }
}

// ---- attention: scores S = QK^T/8 with causal mask ----
__global__ void attn_s_kernel(){
    int bh = blockIdx.y;
    int b = bh >> 3, h = bh & 7;
    int qt = blockIdx.x >> 3, kt = blockIdx.x & 7;
    __shared__ float Qs[32][65];
    __shared__ float Ks[32][65];
    int tid = threadIdx.x;
    {
        int r = tid >> 3, cc = (tid & 7)*8;
        const float* qsrc = g_q + ((size_t)(b*TT + qt*32 + r))*EE + h*DHH + cc;
        const float* ksrc = g_k + ((size_t)(b*TT + kt*32 + r))*EE + h*DHH + cc;
        float4 q0 = *(const float4*)qsrc, q1 = *(const float4*)(qsrc+4);
        float4 k0 = *(const float4*)ksrc, k1 = *(const float4*)(ksrc+4);
        Qs[r][cc+0]=q0.x; Qs[r][cc+1]=q0.y; Qs[r][cc+2]=q0.z; Qs[r][cc+3]=q0.w;
        Qs[r][cc+4]=q1.x; Qs[r][cc+5]=q1.y; Qs[r][cc+6]=q1.z; Qs[r][cc+7]=q1.w;
        Ks[r][cc+0]=k0.x; Ks[r][cc+1]=k0.y; Ks[r][cc+2]=k0.z; Ks[r][cc+3]=k0.w;
        Ks[r][cc+4]=k1.x; Ks[r][cc+5]=k1.y; Ks[r][cc+6]=k1.z; Ks[r][cc+7]=k1.w;
    }
    __syncthreads();
    int r = tid & 31, gq = tid >> 5;
    float a0=0,a1=0,a2=0,a3=0;
    #pragma unroll
    for (int kk=0;kk<64;kk++){
        float qv = Qs[r][kk];
        a0 += qv*Ks[gq*4+0][kk];
        a1 += qv*Ks[gq*4+1][kk];
        a2 += qv*Ks[gq*4+2][kk];
        a3 += qv*Ks[gq*4+3][kk];
    }
    int qrow = qt*32 + r;
    int kc = kt*32 + gq*4;
    float* srow = g_s + ((size_t)bh*TT + qrow)*TT + kc;
    srow[0] = (kc+0<=qrow)? a0*0.125f : -1e30f;
    srow[1] = (kc+1<=qrow)? a1*0.125f : -1e30f;
    srow[2] = (kc+2<=qrow)? a2*0.125f : -1e30f;
    srow[3] = (kc+3<=qrow)? a3*0.125f : -1e30f;
}

// ---- attention: row softmax in-place on g_s ----
__global__ void softmax_kernel(){
    int row = blockIdx.x, tid = threadIdx.x;
    __shared__ float red[256];
    float* sp = g_s + (size_t)row*TT;
    float v = sp[tid];
    red[tid]=v; __syncthreads();
    for (int s=128;s>0;s>>=1){ if (tid<s) red[tid]=fmaxf(red[tid],red[tid+s]); __syncthreads(); }
    float m = red[0]; __syncthreads();
    float e = expf(v-m);
    red[tid]=e; __syncthreads();
    for (int s=128;s>0;s>>=1){ if (tid<s) red[tid]+=red[tid+s]; __syncthreads(); }
    sp[tid] = e / red[0];
}

// ---- attention: O = A @ V ----
__global__ void attn_o_kernel(){
    int bh = blockIdx.y;
    int b = bh >> 3, h = bh & 7;
    int qt = blockIdx.x;
    __shared__ float As[32][65];
    __shared__ float Vs[64][64];
    int tid = threadIdx.x;
    int d = tid & 63, qg = tid >> 6;
    float acc[8];
    #pragma unroll
    for (int i=0;i<8;i++) acc[i]=0.f;
    for (int k0=0;k0<TT;k0+=64){
        {
            int r = tid >> 3, cc = (tid & 7)*8;
            const float* src = g_s + ((size_t)bh*TT + qt*32 + r)*TT + k0 + cc;
            float4 a0=*(const float4*)src, a1=*(const float4*)(src+4);
            As[r][cc+0]=a0.x; As[r][cc+1]=a0.y; As[r][cc+2]=a0.z; As[r][cc+3]=a0.w;
            As[r][cc+4]=a1.x; As[r][cc+5]=a1.y; As[r][cc+6]=a1.z; As[r][cc+7]=a1.w;
        }
        #pragma unroll
        for (int i=0;i<4;i++){
            int fl = (tid + 256*i)*4;
            int r = fl >> 6, cc = fl & 63;
            float4 vv = *(const float4*)(g_v + ((size_t)(b*TT + k0 + r))*EE + h*DHH + cc);
            *(float4*)&Vs[r][cc] = vv;
        }
        __syncthreads();
        #pragma unroll
        for (int kk=0;kk<64;kk++){
            float vv = Vs[kk][d];
            #pragma unroll
            for (int i=0;i<8;i++) acc[i] += As[qg*8+i][kk]*vv;
        }
        __syncthreads();
    }
    #pragma unroll
    for (int i=0;i<8;i++){
        int qr = qt*32 + qg*8 + i;
        g_o[((size_t)(b*TT + qr))*EE + h*DHH + d] = acc[i];
    }
}

// ---- memory init / rv init ----
__global__ void meminit_kernel(const float* __restrict__ mi){
    int idx = blockIdx.x*256 + threadIdx.x;
    g_mem[idx] = mi[idx & (NN*DD - 1)];
}
__global__ void rvzero_kernel(){
    g_rv[blockIdx.x*256 + threadIdx.x] = 0.f;
}

// ---- fused scan step: one kernel per t, one block per (b,h) ----
__global__ void scan_step_kernel(const float* __restrict__ Wr,
                                 const float* __restrict__ pbr,
                                 const float* __restrict__ pbw, int t)
{
    int bh = blockIdx.x;
    int b = bh >> 2, h = bh & 3;
    int tid = threadIdx.x;   // 256

    __shared__ float rv_s[DD];
    __shared__ float ifc_s[256];   // rk[0:64) wk[64:128) wv[128:192) er[192:256)
    __shared__ float knr[HDD], knw[HDD];
    __shared__ float simr[NN], simw[NN], swork[NN];
    __shared__ float gr_sh;
    __shared__ float redv[8]; __shared__ int redi[8];
    __shared__ float kv8[TOPKK];
    __shared__ int s_cnt;
    __shared__ int sel_idx[MAXSEL];
    __shared__ float sel_w[MAXSEL];
    __shared__ float s_inv;

    // 1. load carry rv; record it (old value) into g_cat cols 512..767
    rv_s[tid] = g_rv[b*DD + tid];
    __syncthreads();
    if (h == 0)
        g_cat[(size_t)(b*TT + t)*KCAT + 512 + tid] = rv_s[tid];

    // 2. iface columns needed by this (b,h): i = iface_gemm (has bias) + rv @ W_if_r
    {
        int grp = tid >> 6, l = tid & 63;
        int col = grp*DD + h*HDD + l;
        float acc = g_iface[(size_t)(b*TT + t)*IFF + col];
        #pragma unroll 4
        for (int d=0; d<DD; ++d) acc += rv_s[d]*Wr[(size_t)d*IFF + col];
        ifc_s[tid] = acc;
    }
    if (tid < 32){
        int col = 4*DD + h;
        float acc = 0.f;
        for (int d=tid; d<DD; d+=32) acc += rv_s[d]*Wr[(size_t)d*IFF + col];
        #pragma unroll
        for (int o=16;o>0;o>>=1) acc += __shfl_xor_sync(0xffffffffu, acc, o);
        if (tid==0) gr_sh = acc + g_iface[(size_t)(b*TT + t)*IFF + col];
    }
    __syncthreads();

    // 3. normalize keys
    if (tid < 64){
        int w = tid >> 5, l = tid & 31;
        float v0 = ifc_s[w*64 + l], v1 = ifc_s[w*64 + l + 32];
        float ss = v0*v0 + v1*v1;
        #pragma unroll
        for (int o=16;o>0;o>>=1) ss += __shfl_xor_sync(0xffffffffu, ss, o);
        float rn = rsqrtf(ss + 1e-8f);
        float* dst = w ? knw : knr;
        dst[l] = v0*rn; dst[l+32] = v1*rn;
    }
    __syncthreads();

    // 4. sims: single pass over memory, both keys
    {
        int warp = tid >> 5, lane = tid & 31;
        int oct = lane >> 3, r = lane & 7;
        float4 kr0 = *(const float4*)&knr[r*8], kr1 = *(const float4*)&knr[r*8+4];
        float4 kw0 = *(const float4*)&knw[r*8], kw1 = *(const float4*)&knw[r*8+4];
        for (int it=0; it<NN/32; ++it){
            int n = it*32 + warp*4 + oct;
            const float* mrow = g_mem + (((size_t)b*NN + n)*HMM + h)*HDD + r*8;
            float4 m0 = *(const float4*)mrow, m1 = *(const float4*)(mrow+4);
            float ss = m0.x*m0.x+m0.y*m0.y+m0.z*m0.z+m0.w*m0.w
                     + m1.x*m1.x+m1.y*m1.y+m1.z*m1.z+m1.w*m1.w;
            float dr = m0.x*kr0.x+m0.y*kr0.y+m0.z*kr0.z+m0.w*kr0.w
                     + m1.x*kr1.x+m1.y*kr1.y+m1.z*kr1.z+m1.w*kr1.w;
            float dw = m0.x*kw0.x+m0.y*kw0.y+m0.z*kw0.z+m0.w*kw0.w
                     + m1.x*kw1.x+m1.y*kw1.y+m1.z*kw1.z+m1.w*kw1.w;
            #pragma unroll
            for (int o=4;o>0;o>>=1){
                ss += __shfl_xor_sync(0xffffffffu, ss, o);
                dr += __shfl_xor_sync(0xffffffffu, dr, o);
                dw += __shfl_xor_sync(0xffffffffu, dw, o);
            }
            if (r == 0){
                float rn = rsqrtf(ss + 1e-8f);
                simr[n] = dr*rn;
                simw[n] = dw*rn;
            }
        }
    }
    __syncthreads();

    float beta_r = softplus_clip(*pbr);
    float beta_w = softplus_clip(*pbw);

    for (int phase=0; phase<2; ++phase){
        float beta = phase ? beta_w : beta_r;
        float* sim = phase ? simw : simr;
        for (int i=tid;i<NN;i+=256) swork[i]=sim[i];
        if (tid==0) s_cnt = 0;
        __syncthreads();
        // top-8 via iterative warp-reduced argmax
        for (int it=0; it<TOPKK; ++it){
            float bv = -3.4e38f; int bi = 0;
            #pragma unroll
            for (int j=0;j<NN/256;j++){
                int i = tid + j*256;
                float v = swork[i];
                if (v > bv){ bv=v; bi=i; }
            }
            #pragma unroll
            for (int o=16;o>0;o>>=1){
                float ov = __shfl_xor_sync(0xffffffffu, bv, o);
                int   oi = __shfl_xor_sync(0xffffffffu, bi, o);
                if (ov > bv){ bv=ov; bi=oi; }
            }
            if ((tid&31)==0){ redv[tid>>5]=bv; redi[tid>>5]=bi; }
            __syncthreads();
            if (tid==0){
                float m = redv[0]; int mi = redi[0];
                #pragma unroll
                for (int w=1;w<8;w++) if (redv[w]>m){ m=redv[w]; mi=redi[w]; }
                kv8[it]=m; swork[mi] = -3.4e38f;
            }
            __syncthreads();
        }
        float kth = kv8[TOPKK-1], smax = kv8[0];
        for (int i=tid;i<NN;i+=256){
            float v = sim[i];
            if (v >= kth){
                int p = atomicAdd(&s_cnt, 1);
                if (p < MAXSEL){ sel_idx[p]=i; sel_w[p]=expf(beta*(v-smax)); }
            }
        }
        __syncthreads();
        int cnt = min(s_cnt, MAXSEL);
        if (tid==0){
            float ds=0.f;
            for (int j=0;j<cnt;j++) ds += sel_w[j];
            s_inv = 1.0f/ds;
        }
        __syncthreads();
        float invd = s_inv;
        if (phase==0){
            if (tid < HDD){
                float acc=0.f;
                for (int j=0;j<cnt;j++)
                    acc += sel_w[j]*invd * g_mem[(((size_t)b*NN + sel_idx[j])*HMM + h)*HDD + tid];
                g_rv[b*DD + h*HDD + tid] = acc;
            }
        } else {
            float gg = sigmoid_f(gr_sh);
            int d = tid & 63;
            float ee = sigmoid_f(ifc_s[192 + d]);
            float gv = gg * ifc_s[128 + d];
            for (int j = tid>>6; j<cnt; j+=4){
                float w = sel_w[j]*invd;
                size_t mi = (((size_t)b*NN + sel_idx[j])*HMM + h)*HDD + d;
                g_mem[mi] = g_mem[mi]*(1.0f - w*ee) + w*gv;
            }
        }
        __syncthreads();
    }
}

extern "C" void kernel_launch(void* const* d_in, const int* in_sizes, int n_in,
                              void* d_out, int out_size)
{
    const int*   ids      = (const int*)  d_in[0];
    const float* emb      = (const float*)d_in[1];
    const float* pos      = (const float*)d_in[2];
    const float* ln1_g    = (const float*)d_in[3];
    const float* ln1_b    = (const float*)d_in[4];
    const float* ln2_g    = (const float*)d_in[5];
    const float* ln2_b    = (const float*)d_in[6];
    const float* Wq       = (const float*)d_in[7];
    const float* Wk       = (const float*)d_in[8];
    const float* Wv       = (const float*)d_in[9];
    const float* Wo       = (const float*)d_in[10];
    const float* W1       = (const float*)d_in[11];
    const float* b1       = (const float*)d_in[12];
    const float* W2       = (const float*)d_in[13];
    const float* b2       = (const float*)d_in[14];
    const float* lnf_g    = (const float*)d_in[15];
    const float* lnf_b    = (const float*)d_in[16];
    const float* W_if_h   = (const float*)d_in[17];
    const float* W_if_r   = (const float*)d_in[18];
    const float* b_if     = (const float*)d_in[19];
    const float* W_lg_h   = (const float*)d_in[20];
    const float* W_lg_r   = (const float*)d_in[21];
    const float* b_lg     = (const float*)d_in[22];
    const float* beta_read  = (const float*)d_in[23];
    const float* beta_write = (const float*)d_in[24];
    const float* mem_init = (const float*)d_in[25];
    float* out = (float*)d_out;

    float *px,*phh,*pq,*pk,*pv,*po,*pu,*pif,*pcat;
    cudaGetSymbolAddress((void**)&px,  g_x);
    cudaGetSymbolAddress((void**)&phh, g_h);
    cudaGetSymbolAddress((void**)&pq,  g_q);
    cudaGetSymbolAddress((void**)&pk,  g_k);
    cudaGetSymbolAddress((void**)&pv,  g_v);
    cudaGetSymbolAddress((void**)&po,  g_o);
    cudaGetSymbolAddress((void**)&pu,  g_u);
    cudaGetSymbolAddress((void**)&pif, g_iface);
    cudaGetSymbolAddress((void**)&pcat,g_cat);

    const int M = BB*TT;  // 2048

    embed_kernel<<<M,256>>>(ids, emb, pos);

    for (int l=0; l<LL; ++l){
        ln_kernel<<<M,256>>>(px, ln1_g + l*EE, ln1_b + l*EE, phh, EE);
        tgemm_kernel<false,false,false,false><<<dim3(4,16),256>>>(phh, Wq + (size_t)l*EE*EE, Wq, EE, nullptr, pq, EE, EE, EE);
        tgemm_kernel<false,false,false,false><<<dim3(4,16),256>>>(phh, Wk + (size_t)l*EE*EE, Wk, EE, nullptr, pk, EE, EE, EE);
        tgemm_kernel<false,false,false,false><<<dim3(4,16),256>>>(phh, Wv + (size_t)l*EE*EE, Wv, EE, nullptr, pv, EE, EE, EE);
        attn_s_kernel<<<dim3(64, BB*HAA),256>>>();
        softmax_kernel<<<BB*HAA*TT,256>>>();
        attn_o_kernel<<<dim3(8, BB*HAA),256>>>();
        tgemm_kernel<true,false,false,false><<<dim3(4,16),256>>>(po, Wo + (size_t)l*EE*EE, Wo, EE, nullptr, px, EE, EE, EE);
        ln_kernel<<<M,256>>>(px, ln2_g + l*EE, ln2_b + l*EE, phh, EE);
        tgemm_kernel<false,true,true,false><<<dim3(16,16),256>>>(phh, W1 + (size_t)l*EE*FF, W1, EE, b1 + l*FF, pu, FF, EE, EE);
        tgemm_kernel<true,false,true,false><<<dim3(4,16),256>>>(pu, W2 + (size_t)l*FF*EE, W2, FF, b2 + l*EE, px, EE, FF, FF);
    }

    // final LN -> g_cat cols [0,512) with stride 768
    ln_kernel<<<M,256>>>(px, lnf_g, lnf_b, pcat, KCAT);

    // iface = h @ W_if_h + b_if   (bias folded here; scan adds rv@W_if_r)
    tgemm_kernel<false,false,true,true><<<dim3(9,16),256>>>(pcat, W_if_h, W_if_h, EE, b_if, pif, IFF, EE, KCAT);

    meminit_kernel<<<16384,256>>>(mem_init);
    rvzero_kernel<<<8,256>>>();

    for (int t=0; t<TT; ++t)
        scan_step_kernel<<<BB*HMM,256>>>(W_if_r, beta_read, beta_write, t);

    // out = [h | rv_carry] @ [W_lg_h ; W_lg_r] + b_lg   (single fused vocab GEMM)
    tgemm_kernel<false,false,true,false><<<dim3(250,16),256>>>(pcat, W_lg_h, W_lg_r, EE, b_lg, out, VV, KCAT, KCAT);
}